// round 9
// baseline (speedup 1.0000x reference)
#include <cuda_runtime.h>

// Problem constants (fixed shapes from reference)
#define B_  32
#define C_  64
#define H_  112
#define MH_ 28      // coarse grid = H/4
#define G_  4

// Scratch (no cudaMalloc allowed).
__device__ float         gPool[B_ * C_ * MH_ * MH_];  // pooled means, [b][c][i][j] (6.4 MB)
__device__ unsigned char gA[B_ * MH_ * MH_];          // coarse any-group mask
__device__ unsigned int  g_cnt_mask[B_ * MH_];        // per (b,i) coarse mask count
__device__ unsigned int  g_cnt_dil [B_ * G_];         // per dil-CTA count (128 slots)
__device__ unsigned int  g_ticket;                    // last-CTA ticket (reset each run)

// ---------------------------------------------------------------------------
// Kernel 1: pure streaming 4x4 avg-pool. 1,605,632 cells; 2 cells/thread.
// No syncs, no shared phases -> DRAM never idles; 21 balanced waves.
// cell = ((b*64+c)*28+i)*28+j  (same linear order as gPool layout).
// ---------------------------------------------------------------------------
__global__ __launch_bounds__(256)
void k_pool(const float* __restrict__ x, float* __restrict__ pooled)
{
    const int idx = blockIdx.x * 256 + threadIdx.x;
    #pragma unroll
    for (int half = 0; half < 2; half++) {
        const int cell = idx + half * (B_ * C_ * MH_ * MH_ / 2);   // +802816
        const int j   = cell % 28;
        const int rem = cell / 28;
        const int i   = rem % 28;
        const int bc  = rem / 28;                                  // b*64 + c
        const float* p = x + ((size_t)bc * 112 + i * 4) * 112 + j * 4;
        float s = 0.f;
        #pragma unroll
        for (int r = 0; r < 4; r++) {
            const float4 v = *reinterpret_cast<const float4*>(p + r * 112);
            s += v.x + v.y + v.z + v.w;
        }
        pooled[cell] = s * (1.0f / 16.0f);
    }
}

// ---------------------------------------------------------------------------
// Kernel 2: per (b, coarse-row i): GEMV -> gumbel argmax -> fine mask writes.
// ---------------------------------------------------------------------------
__global__ __launch_bounds__(256)
void k_mask(const float* __restrict__ pooled,
            const float* __restrict__ w,       // (8,64)
            const float* __restrict__ bias,    // (8,)
            const float* __restrict__ gumbel,  // (B,2,G,28,28)
            float* __restrict__ out_mask)      // (B,G,112,112)
{
    const int i   = blockIdx.x;   // coarse row 0..27
    const int b   = blockIdx.y;   // batch
    const int tid = threadIdx.x;

    __shared__ float sw[8 * 64];
    __shared__ float sb[8];
    __shared__ float sm[64 * 28];   // pooled means for this (b, i)
    __shared__ float sl[8 * 28];    // logits
    __shared__ float sM[4 * 28];    // coarse mask (0/1)
    __shared__ unsigned int scnt;

    sw[tid]       = w[tid];
    sw[tid + 256] = w[tid + 256];
    if (tid < 8)  sb[tid] = bias[tid];
    if (tid == 0) scnt = 0u;

    // Load pooled slice: 64 channels x 28 cols = 448 float4 (aligned: 784,28 % 4 == 0)
    const float4* src4 = reinterpret_cast<const float4*>(pooled);
    for (int t = tid; t < 448; t += 256) {
        const int c = t / 7, q = t % 7;
        reinterpret_cast<float4*>(sm)[c * 7 + q] =
            src4[(size_t)(b * 64 + c) * 196 + i * 7 + q];
    }
    __syncthreads();

    // GEMV: logits (8 outputs x 28 cells)
    if (tid < 8 * 28) {
        const int o = tid / 28, j = tid % 28;
        float acc = sb[o];
        #pragma unroll
        for (int c = 0; c < 64; c++)
            acc += sw[o * 64 + c] * sm[c * 28 + j];
        sl[o * 28 + j] = acc;
    }
    __syncthreads();

    // Gumbel argmax -> coarse mask
    if (tid < 4 * 28) {
        const int g = tid / 28, j = tid % 28;
        const float g0 = gumbel[(((size_t)(b * 2 + 0) * 4 + g) * 28 + i) * 28 + j];
        const float g1 = gumbel[(((size_t)(b * 2 + 1) * 4 + g) * 28 + i) * 28 + j];
        const float v0 = sl[g * 28 + j]       + g0;
        const float v1 = sl[(4 + g) * 28 + j] + g1;
        const float m  = (v0 >= v1) ? 1.0f : 0.0f;   // jnp.argmax: first index wins ties
        sM[g * 28 + j] = m;
        if (m > 0.f) atomicAdd(&scnt, 1u);           // smem atomic only
    }
    __syncthreads();

    if (tid < 28) {
        const unsigned char a =
            (sM[tid] != 0.f) | (sM[28 + tid] != 0.f) |
            (sM[56 + tid] != 0.f) | (sM[84 + tid] != 0.f);
        gA[(b * 28 + i) * 28 + tid] = a;
    }
    if (tid == 0) g_cnt_mask[b * 28 + i] = scnt;

    // Fine mask: 4 groups x 4 rows x 28 float4 stores
    for (int t = tid; t < 4 * 4 * 28; t += 256) {
        const int g  = t / 112;
        const int r  = (t / 28) & 3;
        const int cj = t % 28;
        const float v = sM[g * 28 + cj];
        float4* dst = reinterpret_cast<float4*>(
            out_mask + (((size_t)(b * 4 + g) * 112) + (i * 4 + r)) * 112) + cj;
        *dst = make_float4(v, v, v, v);
    }
}

// ---------------------------------------------------------------------------
// Kernel 3: dilation + fused finalize. Grid (4, 32): quarter-of-rows x batch.
// gA[b] cached in smem; float4 stores; per-thread counts + block reduce;
// last CTA (ticket) computes the scalar outputs and resets the ticket.
// ---------------------------------------------------------------------------
__global__ __launch_bounds__(256)
void k_dil(float* __restrict__ out_dil,     // (B,G,112,112)
           float* __restrict__ out_scal)
{
    const int q   = blockIdx.x;   // row quarter: h in [28q, 28q+28)
    const int b   = blockIdx.y;
    const int tid = threadIdx.x;

    __shared__ unsigned char sA[MH_ * MH_];
    __shared__ unsigned int red[256];
    __shared__ int lastFlag;

    for (int t = tid; t < 784; t += 256) sA[t] = gA[b * 784 + t];
    __syncthreads();

    float4* dst4 = reinterpret_cast<float4*>(out_dil);
    unsigned int cnt = 0;
    // items: g(4) x hh(28) x cj(28) = 3136
    #pragma unroll
    for (int it = 0; it < 13; it++) {
        const int t = tid + it * 256;
        if (t < 3136) {
            const int g   = t / 784;
            const int rem = t % 784;
            const int hh  = rem / 28;
            const int cj  = rem % 28;
            const int h   = q * 28 + hh;
            const int ci  = h >> 2;
            const int r0  = ((h & 3) == 0 && ci > 0 ) ? ci - 1 : ci;
            const int r1  = ((h & 3) == 3 && ci < 27) ? ci + 1 : ci;
            const unsigned char mid = sA[r0 * 28 + cj] | sA[r1 * 28 + cj];
            const unsigned char lft = (cj > 0 )
                ? (unsigned char)(mid | sA[r0 * 28 + cj - 1] | sA[r1 * 28 + cj - 1]) : mid;
            const unsigned char rgt = (cj < 27)
                ? (unsigned char)(mid | sA[r0 * 28 + cj + 1] | sA[r1 * 28 + cj + 1]) : mid;
            dst4[(((size_t)(b * 4 + g) * 112) + h) * 28 + cj] =
                make_float4(lft ? 1.f : 0.f, mid ? 1.f : 0.f,
                            mid ? 1.f : 0.f, rgt ? 1.f : 0.f);
            if (g == 0)
                cnt += (lft ? 1u : 0u) + (mid ? 2u : 0u) + (rgt ? 1u : 0u);
        }
    }

    // Block reduce the dil count
    red[tid] = cnt;
    __syncthreads();
    for (int s = 128; s > 0; s >>= 1) {
        if (tid < s) red[tid] += red[tid + s];
        __syncthreads();
    }
    if (tid == 0) {
        g_cnt_dil[b * 4 + q] = red[0];
        __threadfence();                                   // publish before ticket
        lastFlag = (atomicAdd(&g_ticket, 1u) == 127u);
    }
    __syncthreads();

    // Last CTA: finalize scalars, reset ticket (graph-replay determinism)
    if (lastFlag) {
        __threadfence();   // acquire: see all other CTAs' published counts
        // --- mask count reduce (32*28 = 896 slots) ---
        unsigned int am = 0;
        for (int t = tid; t < B_ * MH_; t += 256) am += g_cnt_mask[t];
        red[tid] = am;
        __syncthreads();
        for (int s = 128; s > 0; s >>= 1) {
            if (tid < s) red[tid] += red[tid + s];
            __syncthreads();
        }
        const unsigned int cm = red[0];
        __syncthreads();
        // --- dil count reduce (128 slots) ---
        red[tid] = (tid < B_ * G_) ? g_cnt_dil[tid] : 0u;
        __syncthreads();
        for (int s = 128; s > 0; s >>= 1) {
            if (tid < s) red[tid] += red[tid + s];
            __syncthreads();
        }
        if (tid == 0) {
            // sparsity: fine mean == coarse mean (4x repeat preserves mean)
            out_scal[0] = (float)cm / (float)(B_ * G_ * MH_ * MH_);
            // sparsity_dil: identical across the G output channels
            out_scal[1] = (float)red[0] / (float)(B_ * H_ * H_);
            // flops = C*mh*mw + (8*64 + 64)*mh*mw = 501760
            out_scal[2] = 501760.0f;
            g_ticket = 0u;   // reset for next graph replay
        }
    }
}

extern "C" void kernel_launch(void* const* d_in, const int* in_sizes, int n_in,
                              void* d_out, int out_size)
{
    const float* x      = (const float*)d_in[0];  // (32,64,112,112)
    const float* w      = (const float*)d_in[1];  // (8,64)
    const float* bias   = (const float*)d_in[2];  // (8,)
    const float* gumbel = (const float*)d_in[3];  // (32,2,4,28,28)
    // d_in[4] = temperature: irrelevant to argmax forward values

    float* out = (float*)d_out;
    // Flattened tuple layout: [mask (N) | mask_dil (N) | sparsity, sparsity_dil, flops]
    const long long N = ((long long)out_size - 3) / 2;   // = 32*4*112*112
    float* out_mask = out;
    float* out_dil  = out + N;
    float* out_scal = out + 2 * N;

    float* pooled;
    cudaGetSymbolAddress((void**)&pooled, gPool);

    k_pool<<<(B_ * C_ * MH_ * MH_) / 512, 256>>>(x, pooled);
    {
        dim3 grid(MH_, B_);
        k_mask<<<grid, 256>>>(pooled, w, bias, gumbel, out_mask);
    }
    {
        dim3 grid(4, B_);
        k_dil<<<grid, 256>>>(out_dil, out_scal);
    }
}

// round 10
// speedup vs baseline: 1.1855x; 1.1855x over previous
#include <cuda_runtime.h>

// Problem constants (fixed shapes from reference)
#define B_  32
#define C_  64
#define H_  112
#define MH_ 28      // coarse grid = H/4
#define G_  4

// Scratch (no cudaMalloc allowed).
__device__ unsigned char gA[B_ * MH_ * MH_];          // coarse any-group mask
__device__ unsigned int  g_cnt_mask[B_ * MH_];        // per (b,i) coarse mask count
__device__ unsigned int  g_cnt_dil [B_ * G_];         // per dil-CTA count (128 slots)
__device__ unsigned int  g_ticket;                    // last-CTA ticket (reset each run)

// ---------------------------------------------------------------------------
// Kernel 1 (R4-measured: 22.2us): one CTA per (b, coarse-row i), 256 threads.
//  Phase 1: 4x4 avg-pool of x[b, :, 4i..4i+3, :] -> sm[64][28]  (float4 reads)
//  Phase 2: 8x64 GEMV per coarse cell -> logits[8][28]
//  Phase 3: gumbel argmax -> coarse mask M[4][28]; OR row -> gA; count -> slot
//  Phase 4: fine mask rows 4i..4i+3 for all 4 groups (float4 stores)
// ---------------------------------------------------------------------------
__global__ __launch_bounds__(256)
void k_pool_mask(const float* __restrict__ x,
                 const float* __restrict__ w,       // (8,64)
                 const float* __restrict__ bias,    // (8,)
                 const float* __restrict__ gumbel,  // (B,2,G,28,28)
                 float* __restrict__ out_mask)      // (B,G,112,112)
{
    const int i   = blockIdx.x;   // coarse row 0..27
    const int b   = blockIdx.y;   // batch
    const int tid = threadIdx.x;

    __shared__ float sw[8 * 64];
    __shared__ float sb[8];
    __shared__ float sm[64 * 28];   // pooled means
    __shared__ float sl[8 * 28];    // logits
    __shared__ float sM[4 * 28];    // coarse mask (0/1)
    __shared__ unsigned int scnt;

    // 512 weights, 256 threads -> two loads per thread.
    sw[tid]       = w[tid];
    sw[tid + 256] = w[tid + 256];
    if (tid < 8)  sb[tid] = bias[tid];
    if (tid == 0) scnt = 0u;

    // ---- Phase 1: pooling (HBM-bound term: 112 KB per CTA) ----
    {
        const float* xb = x + ((size_t)b * 64 * 112 + (size_t)i * 4) * 112;
        #pragma unroll
        for (int k = 0; k < 7; k++) {
            const int t = tid + k * 256;
            const int c = t / 28, j = t % 28;
            const float* p = xb + (size_t)c * (112 * 112) + j * 4;
            float s = 0.f;
            #pragma unroll
            for (int r = 0; r < 4; r++) {
                const float4 v = *reinterpret_cast<const float4*>(p + r * 112);
                s += v.x + v.y + v.z + v.w;
            }
            sm[c * 28 + j] = s * (1.0f / 16.0f);
        }
    }
    __syncthreads();

    // ---- Phase 2: logits (8 outputs x 28 cells) ----
    if (tid < 8 * 28) {
        const int o = tid / 28, j = tid % 28;
        float acc = sb[o];
        #pragma unroll
        for (int c = 0; c < 64; c++)
            acc += sw[o * 64 + c] * sm[c * 28 + j];
        sl[o * 28 + j] = acc;
    }
    __syncthreads();

    // ---- Phase 3: gumbel argmax -> coarse mask ----
    if (tid < 4 * 28) {
        const int g = tid / 28, j = tid % 28;
        const float g0 = gumbel[(((size_t)(b * 2 + 0) * 4 + g) * 28 + i) * 28 + j];
        const float g1 = gumbel[(((size_t)(b * 2 + 1) * 4 + g) * 28 + i) * 28 + j];
        const float v0 = sl[g * 28 + j]       + g0;
        const float v1 = sl[(4 + g) * 28 + j] + g1;
        const float m  = (v0 >= v1) ? 1.0f : 0.0f;   // jnp.argmax: first index wins ties
        sM[g * 28 + j] = m;
        if (m > 0.f) atomicAdd(&scnt, 1u);           // smem atomic only
    }
    __syncthreads();

    if (tid < 28) {
        const unsigned char a =
            (sM[tid] != 0.f) | (sM[28 + tid] != 0.f) |
            (sM[56 + tid] != 0.f) | (sM[84 + tid] != 0.f);
        gA[(b * 28 + i) * 28 + tid] = a;
    }
    if (tid == 0) g_cnt_mask[b * 28 + i] = scnt;     // plain store, no ATOMG

    // ---- Phase 4: fine mask, float4 stores (4 groups x 4 rows x 28 float4) ----
    for (int t = tid; t < 4 * 4 * 28; t += 256) {
        const int g  = t / 112;
        const int r  = (t / 28) & 3;
        const int cj = t % 28;
        const float v = sM[g * 28 + cj];
        float4* dst = reinterpret_cast<float4*>(
            out_mask + (((size_t)(b * 4 + g) * 112) + (i * 4 + r)) * 112) + cj;
        *dst = make_float4(v, v, v, v);
    }
}

// ---------------------------------------------------------------------------
// Kernel 2 (R9-verified): dilation + fused finalize. Grid (4, 32), 256 thr.
// gA[b] cached in smem; float4 stores; per-thread counts + block reduce;
// last CTA (ticket) computes the scalar outputs and resets the ticket.
// ---------------------------------------------------------------------------
__global__ __launch_bounds__(256)
void k_dil(float* __restrict__ out_dil,     // (B,G,112,112)
           float* __restrict__ out_scal)
{
    const int q   = blockIdx.x;   // row quarter: h in [28q, 28q+28)
    const int b   = blockIdx.y;
    const int tid = threadIdx.x;

    __shared__ unsigned char sA[MH_ * MH_];
    __shared__ unsigned int red[256];
    __shared__ int lastFlag;

    for (int t = tid; t < 784; t += 256) sA[t] = gA[b * 784 + t];
    __syncthreads();

    float4* dst4 = reinterpret_cast<float4*>(out_dil);
    unsigned int cnt = 0;
    // items: g(4) x hh(28) x cj(28) = 3136
    #pragma unroll
    for (int it = 0; it < 13; it++) {
        const int t = tid + it * 256;
        if (t < 3136) {
            const int g   = t / 784;
            const int rem = t % 784;
            const int hh  = rem / 28;
            const int cj  = rem % 28;
            const int h   = q * 28 + hh;
            const int ci  = h >> 2;
            const int r0  = ((h & 3) == 0 && ci > 0 ) ? ci - 1 : ci;
            const int r1  = ((h & 3) == 3 && ci < 27) ? ci + 1 : ci;
            const unsigned char mid = sA[r0 * 28 + cj] | sA[r1 * 28 + cj];
            const unsigned char lft = (cj > 0 )
                ? (unsigned char)(mid | sA[r0 * 28 + cj - 1] | sA[r1 * 28 + cj - 1]) : mid;
            const unsigned char rgt = (cj < 27)
                ? (unsigned char)(mid | sA[r0 * 28 + cj + 1] | sA[r1 * 28 + cj + 1]) : mid;
            dst4[(((size_t)(b * 4 + g) * 112) + h) * 28 + cj] =
                make_float4(lft ? 1.f : 0.f, mid ? 1.f : 0.f,
                            mid ? 1.f : 0.f, rgt ? 1.f : 0.f);
            if (g == 0)
                cnt += (lft ? 1u : 0u) + (mid ? 2u : 0u) + (rgt ? 1u : 0u);
        }
    }

    // Block reduce the dil count
    red[tid] = cnt;
    __syncthreads();
    for (int s = 128; s > 0; s >>= 1) {
        if (tid < s) red[tid] += red[tid + s];
        __syncthreads();
    }
    if (tid == 0) {
        g_cnt_dil[b * 4 + q] = red[0];
        __threadfence();                                   // publish before ticket
        lastFlag = (atomicAdd(&g_ticket, 1u) == 127u);
    }
    __syncthreads();

    // Last CTA: finalize scalars, reset ticket (graph-replay determinism)
    if (lastFlag) {
        __threadfence();   // acquire: see all other CTAs' published counts
        // --- mask count reduce (32*28 = 896 slots) ---
        unsigned int am = 0;
        for (int t = tid; t < B_ * MH_; t += 256) am += g_cnt_mask[t];
        red[tid] = am;
        __syncthreads();
        for (int s = 128; s > 0; s >>= 1) {
            if (tid < s) red[tid] += red[tid + s];
            __syncthreads();
        }
        const unsigned int cm = red[0];
        __syncthreads();
        // --- dil count reduce (128 slots) ---
        red[tid] = (tid < B_ * G_) ? g_cnt_dil[tid] : 0u;
        __syncthreads();
        for (int s = 128; s > 0; s >>= 1) {
            if (tid < s) red[tid] += red[tid + s];
            __syncthreads();
        }
        if (tid == 0) {
            // sparsity: fine mean == coarse mean (4x repeat preserves mean)
            out_scal[0] = (float)cm / (float)(B_ * G_ * MH_ * MH_);
            // sparsity_dil: identical across the G output channels
            out_scal[1] = (float)red[0] / (float)(B_ * H_ * H_);
            // flops = C*mh*mw + (8*64 + 64)*mh*mw = 501760
            out_scal[2] = 501760.0f;
            g_ticket = 0u;   // reset for next graph replay
        }
    }
}

extern "C" void kernel_launch(void* const* d_in, const int* in_sizes, int n_in,
                              void* d_out, int out_size)
{
    const float* x      = (const float*)d_in[0];  // (32,64,112,112)
    const float* w      = (const float*)d_in[1];  // (8,64)
    const float* bias   = (const float*)d_in[2];  // (8,)
    const float* gumbel = (const float*)d_in[3];  // (32,2,4,28,28)
    // d_in[4] = temperature: irrelevant to argmax forward values

    float* out = (float*)d_out;
    // Flattened tuple layout: [mask (N) | mask_dil (N) | sparsity, sparsity_dil, flops]
    const long long N = ((long long)out_size - 3) / 2;   // = 32*4*112*112
    float* out_mask = out;
    float* out_dil  = out + N;
    float* out_scal = out + 2 * N;

    {
        dim3 grid(MH_, B_);
        k_pool_mask<<<grid, 256>>>(x, w, bias, gumbel, out_mask);
    }
    {
        dim3 grid(4, B_);
        k_dil<<<grid, 256>>>(out_dil, out_scal);
    }
}

// round 12
// speedup vs baseline: 1.3595x; 1.1468x over previous
#include <cuda_runtime.h>

// Problem constants (fixed shapes from reference)
#define B_  32
#define C_  64
#define H_  112
#define MH_ 28      // coarse grid = H/4
#define G_  4

// Scratch (no cudaMalloc allowed).
__device__ unsigned char gA[B_ * MH_ * MH_];   // coarse any-group mask
__device__ unsigned int  g_tot_mask;           // global mask count (atomic)
__device__ unsigned int  g_tot_dil;            // global dil count  (atomic)
__device__ unsigned int  g_ticket;             // last-CTA ticket (reset each run)

// ---------------------------------------------------------------------------
// Kernel 1 (R4-measured 22.2us + gumbel prefetch): one CTA per (b, i), 256 thr.
// ---------------------------------------------------------------------------
__global__ __launch_bounds__(256)
void k_pool_mask(const float* __restrict__ x,
                 const float* __restrict__ w,       // (8,64)
                 const float* __restrict__ bias,    // (8,)
                 const float* __restrict__ gumbel,  // (B,2,G,28,28)
                 float* __restrict__ out_mask)      // (B,G,112,112)
{
    const int i   = blockIdx.x;   // coarse row 0..27
    const int b   = blockIdx.y;   // batch
    const int tid = threadIdx.x;

    __shared__ float sw[8 * 64];
    __shared__ float sb[8];
    __shared__ float sg[224];       // gumbel slice [2][4][28] for (b, i)
    __shared__ float sm[64 * 28];   // pooled means
    __shared__ float sl[8 * 28];    // logits
    __shared__ float sM[4 * 28];    // coarse mask (0/1)
    __shared__ unsigned int scnt;

    // Prefetch gumbel FIRST (issues ahead of the big x burst -> off the tail).
    if (tid < 224) {
        const int o2 = tid / 112, rem = tid % 112;
        const int g = rem / 28, j = rem % 28;
        sg[tid] = gumbel[(((size_t)(b * 2 + o2) * 4 + g) * 28 + i) * 28 + j];
    }
    // 512 weights, 256 threads -> two loads per thread.
    sw[tid]       = w[tid];
    sw[tid + 256] = w[tid + 256];
    if (tid < 8)  sb[tid] = bias[tid];
    if (tid == 0) scnt = 0u;

    // ---- Phase 1: pooling (HBM-bound term: 112 KB per CTA) ----
    {
        const float* xb = x + ((size_t)b * 64 * 112 + (size_t)i * 4) * 112;
        #pragma unroll
        for (int k = 0; k < 7; k++) {
            const int t = tid + k * 256;
            const int c = t / 28, j = t % 28;
            const float* p = xb + (size_t)c * (112 * 112) + j * 4;
            float s = 0.f;
            #pragma unroll
            for (int r = 0; r < 4; r++) {
                const float4 v = *reinterpret_cast<const float4*>(p + r * 112);
                s += v.x + v.y + v.z + v.w;
            }
            sm[c * 28 + j] = s * (1.0f / 16.0f);
        }
    }
    __syncthreads();

    // ---- Phase 2: logits (8 outputs x 28 cells) ----
    if (tid < 8 * 28) {
        const int o = tid / 28, j = tid % 28;
        float acc = sb[o];
        #pragma unroll
        for (int c = 0; c < 64; c++)
            acc += sw[o * 64 + c] * sm[c * 28 + j];
        sl[o * 28 + j] = acc;
    }
    __syncthreads();

    // ---- Phase 3: gumbel argmax -> coarse mask (gumbel from smem) ----
    if (tid < 4 * 28) {
        const int g = tid / 28, j = tid % 28;
        const float v0 = sl[g * 28 + j]       + sg[g * 28 + j];
        const float v1 = sl[(4 + g) * 28 + j] + sg[112 + g * 28 + j];
        const float m  = (v0 >= v1) ? 1.0f : 0.0f;   // jnp.argmax: first index wins ties
        sM[g * 28 + j] = m;
        if (m > 0.f) atomicAdd(&scnt, 1u);           // smem atomic only
    }
    __syncthreads();

    if (tid < 28) {
        const unsigned char a =
            (sM[tid] != 0.f) | (sM[28 + tid] != 0.f) |
            (sM[56 + tid] != 0.f) | (sM[84 + tid] != 0.f);
        gA[(b * 28 + i) * 28 + tid] = a;
    }
    if (tid == 0 && scnt) atomicAdd(&g_tot_mask, scnt);  // one ATOMG per CTA

    // ---- Phase 4: fine mask, float4 stores (4 groups x 4 rows x 28 float4) ----
    for (int t = tid; t < 4 * 4 * 28; t += 256) {
        const int g  = t / 112;
        const int r  = (t / 28) & 3;
        const int cj = t % 28;
        const float v = sM[g * 28 + cj];
        float4* dst = reinterpret_cast<float4*>(
            out_mask + (((size_t)(b * 4 + g) * 112) + (i * 4 + r)) * 112) + cj;
        *dst = make_float4(v, v, v, v);
    }
}

// ---------------------------------------------------------------------------
// Kernel 2 v2: dilation + trivial finalize. Grid (28, 32) = 896 CTAs, 256 thr.
// Per CTA: one coarse row -> 4 fine rows x 4 groups. Row-OR vectors precomputed
// in smem; 2 items/thread; shuffle+smem count reduce; global atomic totals;
// last CTA (ticket) writes the 3 scalars and resets state.
// ---------------------------------------------------------------------------
__global__ __launch_bounds__(256)
void k_dil(float* __restrict__ out_dil,     // (B,G,112,112)
           float* __restrict__ out_scal)
{
    const int i   = blockIdx.x;   // coarse row
    const int b   = blockIdx.y;
    const int tid = threadIdx.x;

    __shared__ unsigned char rT[MH_], rM[MH_], rB[MH_];
    __shared__ unsigned int warpsum[8];

    if (tid < 28) {
        const unsigned char* Ab = gA + (size_t)b * 784;
        const unsigned char m = Ab[i * 28 + tid];
        rM[tid] = m;
        rT[tid] = (i > 0 ) ? (unsigned char)(Ab[(i - 1) * 28 + tid] | m) : m;
        rB[tid] = (i < 27) ? (unsigned char)(Ab[(i + 1) * 28 + tid] | m) : m;
    }
    __syncthreads();

    unsigned int cnt = 0;
    // items: r(4) x g(4) x cj(28) = 448; threads handle t and t+256.
    #pragma unroll
    for (int it = 0; it < 2; it++) {
        const int t = tid + it * 256;
        if (t < 448) {
            const int r   = t / 112;
            const int rem = t % 112;
            const int g   = rem / 28;
            const int cj  = rem % 28;
            const unsigned char* row = (r == 0) ? rT : ((r == 3) ? rB : rM);
            const unsigned char mid = row[cj];
            const unsigned char lft = (cj > 0 ) ? (unsigned char)(mid | row[cj - 1]) : mid;
            const unsigned char rgt = (cj < 27) ? (unsigned char)(mid | row[cj + 1]) : mid;
            const int h = i * 4 + r;
            reinterpret_cast<float4*>(out_dil)[
                ((size_t)(b * 4 + g) * 112 + h) * 28 + cj] =
                make_float4(lft ? 1.f : 0.f, mid ? 1.f : 0.f,
                            mid ? 1.f : 0.f, rgt ? 1.f : 0.f);
            if (g == 0)
                cnt += (lft ? 1u : 0u) + (mid ? 2u : 0u) + (rgt ? 1u : 0u);
        }
    }

    // warp shuffle reduce, then cross-warp via smem
    #pragma unroll
    for (int off = 16; off > 0; off >>= 1)
        cnt += __shfl_down_sync(0xffffffffu, cnt, off);
    if ((tid & 31) == 0) warpsum[tid >> 5] = cnt;
    __syncthreads();

    if (tid == 0) {
        unsigned int s = 0;
        #pragma unroll
        for (int wdx = 0; wdx < 8; wdx++) s += warpsum[wdx];
        if (s) atomicAdd(&g_tot_dil, s);
        __threadfence();                               // publish before ticket
        if (atomicAdd(&g_ticket, 1u) == (MH_ * B_ - 1u)) {
            __threadfence();                           // acquire all totals
            const unsigned int cm = g_tot_mask;
            const unsigned int cd = g_tot_dil;
            // sparsity: fine mean == coarse mean (4x repeat preserves mean)
            out_scal[0] = (float)cm / (float)(B_ * G_ * MH_ * MH_);
            // sparsity_dil: identical across the G output channels
            out_scal[1] = (float)cd / (float)(B_ * H_ * H_);
            // flops = C*mh*mw + (8*64 + 64)*mh*mw = 501760
            out_scal[2] = 501760.0f;
            g_tot_mask = 0u;                           // reset for next replay
            g_tot_dil  = 0u;
            __threadfence();
            g_ticket   = 0u;
        }
    }
}

extern "C" void kernel_launch(void* const* d_in, const int* in_sizes, int n_in,
                              void* d_out, int out_size)
{
    const float* x      = (const float*)d_in[0];  // (32,64,112,112)
    const float* w      = (const float*)d_in[1];  // (8,64)
    const float* bias   = (const float*)d_in[2];  // (8,)
    const float* gumbel = (const float*)d_in[3];  // (32,2,4,28,28)
    // d_in[4] = temperature: irrelevant to argmax forward values

    float* out = (float*)d_out;
    // Flattened tuple layout: [mask (N) | mask_dil (N) | sparsity, sparsity_dil, flops]
    const long long N = ((long long)out_size - 3) / 2;   // = 32*4*112*112
    float* out_mask = out;
    float* out_dil  = out + N;
    float* out_scal = out + 2 * N;

    {
        dim3 grid(MH_, B_);
        k_pool_mask<<<grid, 256>>>(x, w, bias, gumbel, out_mask);
    }
    {
        dim3 grid(MH_, B_);
        k_dil<<<grid, 256>>>(out_dil, out_scal);
    }
}